// round 11
// baseline (speedup 1.0000x reference)
#include <cuda_runtime.h>
#include <cuda_bf16.h>
#include <math.h>
#include <stdint.h>

#define TE 128
#define THREADS 512

// ---- smem layout (32-bit word offsets), per CTA = 112.64KB -> 2 CTAs/SM ----
#define OFF_W0    0        // fp32 [8][64] folded 1/sqrt(8)            512
// union region: A-frags + EMBT alias MIXS
#define OFF_AHI   512      // A hi frag units [8 ms][4 k][8 g][4 tq]   4096
#define OFF_ALO   4608     // A lo                                     4096
#define OFF_EMBT  8704     // fp32 [8][128]                            1024
#define OFF_MIXS  512      // fp32 [128][112] gates (aliases above)    14336
#define OFF_US    14848    // [128][4] unit vectors                    512
#define OFF_SVS   15360    // [128][84] gathered sender s|v            10752
#define OFF_DOTS  26112    // [128][16] v.u                            2048
#define MIX_STRIDE 112
#define SMEM_FLOATS 28160
#define SMEM_BYTES (SMEM_FLOATS * 4)   // 112640 B

// ---- B2/B3 packed weights in global (L2-resident), filled by pack kernel ----
// unit idx = row*16 + k*4 + tq ; unit = [bh0, bh1, bl0, bl1]
__device__ __align__(16) unsigned int gB2w[64 * 64];    // 4096 words
__device__ __align__(16) unsigned int gB3w[112 * 64];   // 7168 words

__device__ __forceinline__ float swishf(float x) {
    return x * (1.0f / (1.0f + __expf(-x)));
}

__device__ __forceinline__ void split2(float x0, float x1, uint32_t& h, uint32_t& l) {
    __nv_bfloat162 hb = __floats2bfloat162_rn(x0, x1);
    float r0 = x0 - __bfloat162float(hb.x);
    float r1 = x1 - __bfloat162float(hb.y);
    __nv_bfloat162 lb = __floats2bfloat162_rn(r0, r1);
    h = *(uint32_t*)&hb;
    l = *(uint32_t*)&lb;
}

__device__ __forceinline__ void mma_bf16(float* d, uint32_t a0, uint32_t a1,
                                         uint32_t a2, uint32_t a3,
                                         uint32_t b0, uint32_t b1) {
    asm volatile(
        "mma.sync.aligned.m16n8k16.row.col.f32.bf16.bf16.f32 "
        "{%0,%1,%2,%3}, {%4,%5,%6,%7}, {%8,%9}, {%0,%1,%2,%3};"
        : "+f"(d[0]), "+f"(d[1]), "+f"(d[2]), "+f"(d[3])
        : "r"(a0), "r"(a1), "r"(a2), "r"(a3), "r"(b0), "r"(b1));
}

extern "C" __global__ void pack_weights(const float* __restrict__ W1,
                                        const float* __restrict__ W2)
{
    int tid = blockIdx.x * blockDim.x + threadIdx.x;
    int stride = gridDim.x * blockDim.x;
    for (int i = tid; i < 64 * 32; i += stride) {          // B2[n][k] = W1[k][n]/8
        int n = i >> 5, wd = i & 31;
        int k = wd >> 3, r = wd & 7, tq = r & 3, half = r >> 2;
        float x0 = W1[(2*wd)   * 64 + n] * 0.125f;
        float x1 = W1[(2*wd+1) * 64 + n] * 0.125f;
        uint32_t hw, lw;
        split2(x0, x1, hw, lw);
        int base = (n * 16 + k * 4 + tq) * 4;
        gB2w[base + half] = hw;
        gB2w[base + 2 + half] = lw;
    }
    for (int i = tid; i < 112 * 32; i += stride) {         // B3[n][k] = W2[k][n]*scl(n)
        int n = i >> 5, wd = i & 31;
        int k = wd >> 3, r = wd & 7, tq = r & 3, half = r >> 2;
        float scl = (n >= 96) ? 0.03125f * 1.224744871391589f : 0.03125f;
        float x0 = W2[(2*wd)   * 112 + n] * scl;
        float x1 = W2[(2*wd+1) * 112 + n] * scl;
        uint32_t hw, lw;
        split2(x0, x1, hw, lw);
        int base = (n * 16 + k * 4 + tq) * 4;
        gB3w[base + half] = hw;
        gB3w[base + 2 + half] = lw;
    }
}

extern "C" __global__ void __launch_bounds__(THREADS, 2)
mp_kernel(const float* __restrict__ vectors,
          const float* __restrict__ node_s,
          const float* __restrict__ node_v,
          const float* __restrict__ W0,
          const int* __restrict__ senders,
          const int* __restrict__ receivers,
          float* __restrict__ out,
          int E, int numTiles)
{
    extern __shared__ float sm[];
    uint32_t* smw = (uint32_t*)sm;
    const int t = threadIdx.x;

    for (int i = t; i < 512; i += THREADS) sm[OFF_W0 + i] = W0[i] * 0.35355339059327373f;
    __syncthreads();

    const int w = t >> 5, lane = t & 31;
    const int g = lane >> 2, tq = lane & 3;
    const int ms = w >> 1, nq = w & 1;           // 8 M-strips x 2 N-halves
    const int mb = ms * 16;
    const int aunit0 = (ms * 128 + g * 4 + tq) * 4;   // + k*128 words

    const uint32_t* abh = smw + OFF_AHI + aunit0;
    const uint32_t* abl = smw + OFF_ALO + aunit0;
    const uint4* gb2 = ((const uint4*)gB2w) + ((nq * 32 + g) * 16 + tq);  // + n*128 + k*4
    const uint4* gb3 = ((const uint4*)gB3w) + ((nq * 56 + g) * 16 + tq);  // + n*128 + k*4
    const int nb3 = nq * 56;

    for (int tile = blockIdx.x; tile < numTiles; tile += gridDim.x) {
        const int e0 = tile * TE;

        // ---- stage A: geometry + radial (Bessel*envelope) embedding ----
        if (t < TE) {
            int e = e0 + t;
            float vx = 0.f, vy = 0.f, vz = 0.f;
            if (e < E) { vx = vectors[3*e+0]; vy = vectors[3*e+1]; vz = vectors[3*e+2]; }
            float r = sqrtf(vx*vx + vy*vy + vz*vz);
            float rinv = (r > 1e-12f) ? 1.0f / r : 0.0f;
            sm[OFF_US + 4*t+0] = vx*rinv; sm[OFF_US + 4*t+1] = vy*rinv;
            sm[OFF_US + 4*t+2] = vz*rinv; sm[OFF_US + 4*t+3] = 0.f;
            float env = 0.0f;
            if (r < 1.0f) {
                float x2 = r*r, x4 = x2*x2, x6 = x4*x2, x7 = x6*r, x8 = x4*x4;
                env = 1.0f - 28.0f*x6 + 48.0f*x7 - 21.0f*x8;
            }
            float pref = (r > 0.0f) ? 1.4142135623730951f * rinv * env : 0.0f;
            float s1, c1;
            sincosf(3.14159265358979323846f * r, &s1, &c1);
            float sn = s1, sp = 0.0f, c2 = 2.0f * c1;
            #pragma unroll
            for (int n = 0; n < 8; n++) {
                sm[OFF_EMBT + n*TE + t] = pref * sn;
                float nx = c2 * sn - sp; sp = sn; sn = nx;
            }
        }
        // gather issue, 4 threads/edge (latency hidden behind stage B)
        const int ge = t >> 2, gsub = t & 3;
        const int geg = e0 + ge;
        const bool gok = (geg < E);
        int snd = gok ? senders[geg] : 0;
        const float4* sp4 = (const float4*)(node_s + (size_t)snd * 32);
        const float4* vp4 = (const float4*)(node_v + (size_t)snd * 48);
        float4 gr[5];
        #pragma unroll
        for (int q = 0; q < 5; q++) {
            int f4i = gsub + 4*q;                 // 0..19
            float4 val = {0.f, 0.f, 0.f, 0.f};
            if (gok) val = (f4i < 8) ? sp4[f4i] : vp4[f4i - 8];
            gr[q] = val;
        }
        __syncthreads();

        // ---- stage B: GEMM1 (FFMA, K=8), 32 cols/warp -> A units k=2nq,2nq+1 ----
        {
            const int nb = nq * 32;
            float acc[2][4][2];
            #pragma unroll
            for (int a = 0; a < 2; a++)
                #pragma unroll
                for (int b = 0; b < 4; b++) { acc[a][b][0] = 0.f; acc[a][b][1] = 0.f; }
            #pragma unroll
            for (int k = 0; k < 8; k++) {
                float e0v = sm[OFF_EMBT + k*TE + mb + g];
                float e1v = sm[OFF_EMBT + k*TE + mb + 8 + g];
                #pragma unroll
                for (int nt = 0; nt < 4; nt++) {
                    float2 wv = *(const float2*)(sm + OFF_W0 + k*64 + nb + nt*8 + 2*tq);
                    acc[0][nt][0] += e0v * wv.x; acc[0][nt][1] += e0v * wv.y;
                    acc[1][nt][0] += e1v * wv.x; acc[1][nt][1] += e1v * wv.y;
                }
            }
            #pragma unroll
            for (int kidx = 0; kidx < 2; kidx++) {
                int k = nq * 2 + kidx;
                int n0 = 2 * kidx, n1 = n0 + 1;
                uint32_t h0,l0,h1,l1,h2,l2,h3,l3;
                split2(swishf(acc[0][n0][0]), swishf(acc[0][n0][1]), h0, l0);
                split2(swishf(acc[1][n0][0]), swishf(acc[1][n0][1]), h1, l1);
                split2(swishf(acc[0][n1][0]), swishf(acc[0][n1][1]), h2, l2);
                split2(swishf(acc[1][n1][0]), swishf(acc[1][n1][1]), h3, l3);
                *(uint4*)(abh + k * 128) = make_uint4(h0, h1, h2, h3);
                *(uint4*)(abl + k * 128) = make_uint4(l0, l1, l2, l3);
            }
        }
        // land gather into smem; compute dots (4 per thread)
        {
            float* dst = sm + OFF_SVS + ge * 84;
            #pragma unroll
            for (int q = 0; q < 5; q++) *(float4*)(dst + 4 * (gsub + 4*q)) = gr[q];
            __syncwarp();
            const float* usf = sm + OFF_US + 4 * ge;
            float ux = usf[0], uy = usf[1], uz = usf[2];
            #pragma unroll
            for (int q = 0; q < 4; q++) {
                int c = 4 * gsub + q;
                const float* vv = dst + 32 + 3 * c;
                sm[OFF_DOTS + ge * 16 + c] = ux*vv[0] + uy*vv[1] + uz*vv[2];
            }
        }
        __syncthreads();

        // ---- stage C: GEMM2 via bf16 mma (3-pass split), M128 N64 K64 ----
        float acc2[4][4];
        {
            #pragma unroll
            for (int n = 0; n < 4; n++)
                #pragma unroll
                for (int j = 0; j < 4; j++) acc2[n][j] = 0.f;
            #pragma unroll
            for (int k = 0; k < 4; k++) {
                uint4 ah = *(const uint4*)(abh + k * 128);
                uint4 al = *(const uint4*)(abl + k * 128);
                #pragma unroll
                for (int n = 0; n < 4; n++) {
                    uint4 b = gb2[n * 128 + k * 4];
                    mma_bf16(acc2[n], ah.x, ah.y, ah.z, ah.w, b.x, b.y);
                    mma_bf16(acc2[n], ah.x, ah.y, ah.z, ah.w, b.z, b.w);
                    mma_bf16(acc2[n], al.x, al.y, al.z, al.w, b.x, b.y);
                }
            }
        }
        __syncthreads();   // all h1 reads done before overwrite

        // ---- stage D: swish(h2), split -> A units k=2nq,2nq+1 ----
        {
            #pragma unroll
            for (int kidx = 0; kidx < 2; kidx++) {
                int k = nq * 2 + kidx;
                int n0 = 2 * kidx, n1 = n0 + 1;
                uint32_t h0,l0,h1,l1,h2,l2,h3,l3;
                split2(swishf(acc2[n0][0]), swishf(acc2[n0][1]), h0, l0);
                split2(swishf(acc2[n0][2]), swishf(acc2[n0][3]), h1, l1);
                split2(swishf(acc2[n1][0]), swishf(acc2[n1][1]), h2, l2);
                split2(swishf(acc2[n1][2]), swishf(acc2[n1][3]), h3, l3);
                *(uint4*)(abh + k * 128) = make_uint4(h0, h1, h2, h3);
                *(uint4*)(abl + k * 128) = make_uint4(l0, l1, l2, l3);
            }
        }
        __syncthreads();

        // ---- stage E: GEMM3 via bf16 mma (3-pass split), M128 N112 K64 ----
        {
            float acc3[7][4];
            #pragma unroll
            for (int n = 0; n < 7; n++)
                #pragma unroll
                for (int j = 0; j < 4; j++) acc3[n][j] = 0.f;
            #pragma unroll
            for (int k = 0; k < 4; k++) {
                uint4 ah = *(const uint4*)(abh + k * 128);
                uint4 al = *(const uint4*)(abl + k * 128);
                #pragma unroll
                for (int n = 0; n < 7; n++) {
                    uint4 b = gb3[n * 128 + k * 4];
                    mma_bf16(acc3[n], ah.x, ah.y, ah.z, ah.w, b.x, b.y);
                    mma_bf16(acc3[n], ah.x, ah.y, ah.z, ah.w, b.z, b.w);
                    mma_bf16(acc3[n], al.x, al.y, al.z, al.w, b.x, b.y);
                }
            }
            __syncthreads();   // A/EMBT fully read before gate store aliases them
            #pragma unroll
            for (int n = 0; n < 7; n++) {
                int col = nb3 + n*8 + 2*tq;
                *(float2*)(sm + OFF_MIXS + (mb + g) * MIX_STRIDE + col) =
                    make_float2(acc3[n][0], acc3[n][1]);
                *(float2*)(sm + OFF_MIXS + (mb + g + 8) * MIX_STRIDE + col) =
                    make_float2(acc3[n][2], acc3[n][3]);
            }
        }
        __syncthreads();

        // ---- stage G: message formation + atomic scatter, 4 threads/edge ----
        {
            const int e = t >> 2, sub = t & 3;
            const int eg2 = e0 + e;
            const bool ok = (eg2 < E);
            int rec = ok ? receivers[eg2] : 0;
            const float* dst = sm + OFF_SVS + e * 84;
            const float* usf = sm + OFF_US + 4 * e;
            const float* dts = sm + OFF_DOTS + e * 16;
            const float* mx  = sm + OFF_MIXS + e * MIX_STRIDE;
            float* obase = out + (size_t)rec * 240;
            const float ux = usf[0], uy = usf[1], uz = usf[2];

            #pragma unroll
            for (int it = 0; it < 15; it++) {
                const int gg = 4 * it + sub;   // warp-uniform region per it
                float4 val;
                if (it < 2) {                  // msg_s: s * gate
                    float4 s4 = *(const float4*)(dst + 4 * gg);
                    float4 m4 = *(const float4*)(mx + 4 * gg);
                    val.x = s4.x*m4.x; val.y = s4.y*m4.y; val.z = s4.z*m4.z; val.w = s4.w*m4.w;
                } else if (it == 2) {          // msg_s: (v.u) * gate
                    float4 d4 = *(const float4*)(dts + 4 * sub);
                    float4 m4 = *(const float4*)(mx + 4 * gg);
                    val.x = d4.x*m4.x; val.y = d4.y*m4.y; val.z = d4.z*m4.z; val.w = d4.w*m4.w;
                } else {                       // msg_v flat regions
                    const int j0 = 16 * it + 4 * sub - 48;
                    const int ch0 = j0 / 3;
                    const int i0 = j0 - 3 * ch0;
                    const float m0 = mx[48 + ch0];
                    const float m1 = mx[48 + ch0 + 1];
                    float tmp[4];
                    if (it < 6) {              // filtered v (ch 0..15)
                        float4 vv = *(const float4*)(dst + 32 + j0);
                        float vvq[4] = {vv.x, vv.y, vv.z, vv.w};
                        #pragma unroll
                        for (int q = 0; q < 4; q++) {
                            bool cross = (i0 + q) >= 3;
                            tmp[q] = vvq[q] * (cross ? m1 : m0);
                        }
                    } else if (it < 12) {      // s x Y1 (ch 16..47)
                        float s0 = dst[ch0 - 16];
                        float s1 = dst[ch0 - 15];
                        #pragma unroll
                        for (int q = 0; q < 4; q++) {
                            bool cross = (i0 + q) >= 3;
                            int i = i0 + q - (cross ? 3 : 0);
                            float u = (i == 0) ? ux : ((i == 1) ? uy : uz);
                            tmp[q] = (cross ? s1 : s0) * u * (cross ? m1 : m0);
                        }
                    } else {                   // v x Y2 (ch 48..63), sqrt1.5 folded in gate
                        int jj = j0 - 144;
                        float4 vv = *(const float4*)(dst + 32 + jj);
                        float vvq[4] = {vv.x, vv.y, vv.z, vv.w};
                        float d0 = dts[ch0 - 48];
                        float d1 = (ch0 < 63) ? dts[ch0 - 47] : d0;
                        #pragma unroll
                        for (int q = 0; q < 4; q++) {
                            bool cross = (i0 + q) >= 3;
                            int i = i0 + q - (cross ? 3 : 0);
                            float u = (i == 0) ? ux : ((i == 1) ? uy : uz);
                            float dd = cross ? d1 : d0;
                            tmp[q] = (u * dd - vvq[q] * 0.3333333333333333f) * (cross ? m1 : m0);
                        }
                    }
                    val.x = tmp[0]; val.y = tmp[1]; val.z = tmp[2]; val.w = tmp[3];
                }
                if (ok) {
                    float* addr = obase + 4 * gg;
                    asm volatile("red.global.add.v4.f32 [%0], {%1,%2,%3,%4};"
                                 :: "l"(addr), "f"(val.x), "f"(val.y), "f"(val.z), "f"(val.w)
                                 : "memory");
                }
            }
        }
        __syncthreads();   // smem reused next tile
    }
}

extern "C" void kernel_launch(void* const* d_in, const int* in_sizes, int n_in,
                              void* d_out, int out_size) {
    const float* vectors   = (const float*)d_in[0];
    const float* node_s    = (const float*)d_in[1];
    const float* node_v    = (const float*)d_in[2];
    const float* W0        = (const float*)d_in[3];
    const float* W1        = (const float*)d_in[4];
    const float* W2        = (const float*)d_in[5];
    const int*   senders   = (const int*)d_in[6];
    const int*   receivers = (const int*)d_in[7];
    float*       out       = (float*)d_out;

    int E = in_sizes[6];
    int numTiles = (E + TE - 1) / TE;

    cudaFuncSetAttribute(mp_kernel, cudaFuncAttributeMaxDynamicSharedMemorySize, SMEM_BYTES);

    pack_weights<<<16, 512>>>(W1, W2);
    cudaMemsetAsync(d_out, 0, (size_t)out_size * sizeof(float), 0);

    int grid = 296;                      // persistent: 2 CTAs/SM, 32 warps/SM
    if (grid > numTiles) grid = numTiles;
    mp_kernel<<<grid, THREADS, SMEM_BYTES>>>(vectors, node_s, node_v, W0,
                                             senders, receivers, out, E, numTiles);
}

// round 13
// speedup vs baseline: 1.1269x; 1.1269x over previous
#include <cuda_runtime.h>
#include <cuda_bf16.h>
#include <math.h>
#include <stdint.h>

#define TE 64
#define THREADS 512

// ---- smem layout (32-bit word offsets) ----
#define OFF_W0    0        // fp32 [8][64] folded 1/sqrt(8)               512
#define OFF_B2    512      // packed units [64 n][4 k][4 tq][16B]         4096
#define OFF_B3    4608     // packed units [112 n][4 k][4 tq][16B]        7168
// union region: A-frags + EMBT alias MIXS
#define OFF_AHI   11776    // A hi frag units [4 ms][4 k][8 g][4 tq]      2048
#define OFF_ALO   13824    // A lo                                        2048
#define OFF_EMBT  15872    // fp32 [8][64]                                512
#define OFF_MIXS  11776    // fp32 [64][116] gates (aliases above)        7424
#define OFF_US    19200    // [64][4]                                     256
#define OFF_SVS   19456    // [64][84]                                    5376
#define OFF_DOTS  24832    // [64][20] (stride 20: conflict-free)         1280
#define MIX_STRIDE 116
#define SMEM_FLOATS 26112
#define SMEM_BYTES (SMEM_FLOATS * 4)   // 104448 B -> 2 CTAs/SM

__device__ __forceinline__ float swishf(float x) {
    return x * (1.0f / (1.0f + __expf(-x)));
}

__device__ __forceinline__ void split2(float x0, float x1, uint32_t& h, uint32_t& l) {
    __nv_bfloat162 hb = __floats2bfloat162_rn(x0, x1);
    float r0 = x0 - __bfloat162float(hb.x);
    float r1 = x1 - __bfloat162float(hb.y);
    __nv_bfloat162 lb = __floats2bfloat162_rn(r0, r1);
    h = *(uint32_t*)&hb;
    l = *(uint32_t*)&lb;
}

__device__ __forceinline__ void mma_bf16(float* d, uint32_t a0, uint32_t a1,
                                         uint32_t a2, uint32_t a3,
                                         uint32_t b0, uint32_t b1) {
    asm volatile(
        "mma.sync.aligned.m16n8k16.row.col.f32.bf16.bf16.f32 "
        "{%0,%1,%2,%3}, {%4,%5,%6,%7}, {%8,%9}, {%0,%1,%2,%3};"
        : "+f"(d[0]), "+f"(d[1]), "+f"(d[2]), "+f"(d[3])
        : "r"(a0), "r"(a1), "r"(a2), "r"(a3), "r"(b0), "r"(b1));
}

__device__ __forceinline__ void cp16(uint32_t saddr, const void* gptr) {
    asm volatile("cp.async.ca.shared.global [%0], [%1], 16;"
                 :: "r"(saddr), "l"(gptr) : "memory");
}
#define CP_COMMIT() asm volatile("cp.async.commit_group;" ::: "memory")
#define CP_WAIT0()  asm volatile("cp.async.wait_group 0;" ::: "memory")

extern "C" __global__ void __launch_bounds__(THREADS, 2)
mp_kernel(const float* __restrict__ vectors,
          const float* __restrict__ node_s,
          const float* __restrict__ node_v,
          const float* __restrict__ W0,
          const float* __restrict__ W1,
          const float* __restrict__ W2,
          const int* __restrict__ senders,
          const int* __restrict__ receivers,
          float* __restrict__ out,
          int E, int numTiles)
{
    extern __shared__ float sm[];
    uint32_t* smw = (uint32_t*)sm;
    const int t = threadIdx.x;

    // ---- one-time weight staging (packed 16B units, swizzled) ----
    for (int i = t; i < 512; i += THREADS) sm[OFF_W0 + i] = W0[i] * 0.35355339059327373f;
    for (int i = t; i < 64 * 32; i += THREADS) {      // B2[n][k] = W1[k][n]/8
        int n = i >> 5, wd = i & 31;
        int k = wd >> 3, r = wd & 7, tq = r & 3, half = r >> 2;
        float x0 = W1[(2*wd)   * 64 + n] * 0.125f;
        float x1 = W1[(2*wd+1) * 64 + n] * 0.125f;
        uint32_t hw, lw;
        split2(x0, x1, hw, lw);
        int kk = (k + n) & 3;
        int base = OFF_B2 + (n * 16 + kk * 4 + tq) * 4;
        smw[base + half] = hw;
        smw[base + 2 + half] = lw;
    }
    for (int i = t; i < 112 * 32; i += THREADS) {     // B3[n][k] = W2[k][n]*scl(n)
        int n = i >> 5, wd = i & 31;
        int k = wd >> 3, r = wd & 7, tq = r & 3, half = r >> 2;
        float scl = (n >= 96) ? 0.03125f * 1.224744871391589f : 0.03125f;
        float x0 = W2[(2*wd)   * 112 + n] * scl;
        float x1 = W2[(2*wd+1) * 112 + n] * scl;
        uint32_t hw, lw;
        split2(x0, x1, hw, lw);
        int kk = (k + n) & 3;
        int base = OFF_B3 + (n * 16 + kk * 4 + tq) * 4;
        smw[base + half] = hw;
        smw[base + 2 + half] = lw;
    }
    __syncthreads();

    const int w = t >> 5, lane = t & 31;
    const int g = lane >> 2, tq = lane & 3;
    const int ms = w >> 2, nq = w & 3;           // 4 M-strips x 4 N-quarters
    const int mb = ms * 16;
    const int aunit0 = (ms * 128 + g * 4 + tq) * 4;   // + k*128 words

    // thread-constant base pointers
    const uint32_t* abh = smw + OFF_AHI + aunit0;
    const uint32_t* abl = smw + OFF_ALO + aunit0;
    const int nb2 = nq * 16;
    const int r2 = (nb2 + g) & 3;
    const uint32_t* bb2 = smw + OFF_B2 + (nb2 + g) * 64 + tq * 4;   // + n*512 + kk*16
    const int nb3 = (nq < 2) ? 32 * nq : 64 + 24 * (nq - 2);
    const int nt3 = (nq < 2) ? 4 : 3;
    const int r3 = (nb3 + g) & 3;
    const uint32_t* bb3 = smw + OFF_B3 + (nb3 + g) * 64 + tq * 4;   // + n*512 + kk*16

    // gather identity (8 threads/edge)
    const int ge = t >> 3, gsub = t & 7;
    float* gdst = sm + OFF_SVS + ge * 84;

    for (int tile = blockIdx.x; tile < numTiles; tile += gridDim.x) {
        const int e0 = tile * TE;

        // ---- stage A: geometry + radial embedding (warps 0-1) ----
        if (t < TE) {
            int e = e0 + t;
            float vx = 0.f, vy = 0.f, vz = 0.f;
            if (e < E) { vx = vectors[3*e+0]; vy = vectors[3*e+1]; vz = vectors[3*e+2]; }
            float r = sqrtf(vx*vx + vy*vy + vz*vz);
            float rinv = (r > 1e-12f) ? 1.0f / r : 0.0f;
            sm[OFF_US + 4*t+0] = vx*rinv; sm[OFF_US + 4*t+1] = vy*rinv;
            sm[OFF_US + 4*t+2] = vz*rinv; sm[OFF_US + 4*t+3] = 0.f;
            float env = 0.0f;
            if (r < 1.0f) {
                float x2 = r*r, x4 = x2*x2, x6 = x4*x2, x7 = x6*r, x8 = x4*x4;
                env = 1.0f - 28.0f*x6 + 48.0f*x7 - 21.0f*x8;
            }
            float pref = (r > 0.0f) ? 1.4142135623730951f * rinv * env : 0.0f;
            float s1, c1;
            sincosf(3.14159265358979323846f * r, &s1, &c1);
            float sn = s1, sp = 0.0f, c2 = 2.0f * c1;
            #pragma unroll
            for (int n = 0; n < 8; n++) {
                sm[OFF_EMBT + n*TE + t] = pref * sn;
                float nx = c2 * sn - sp; sp = sn; sn = nx;
            }
        }
        // ---- gather via cp.async (global -> smem direct), 8 threads/edge ----
        {
            const int geg = e0 + ge;
            if (geg < E) {
                int snd = senders[geg];
                const float4* sp4 = (const float4*)(node_s + (size_t)snd * 32);
                const float4* vp4 = (const float4*)(node_v + (size_t)snd * 48);
                #pragma unroll
                for (int q = 0; q < 3; q++) {
                    int f4i = gsub + 8*q;                 // 0..23, valid < 20
                    if (f4i < 20) {
                        uint32_t sa = (uint32_t)__cvta_generic_to_shared(gdst + 4*f4i);
                        cp16(sa, (f4i < 8) ? (const void*)(sp4 + f4i)
                                           : (const void*)(vp4 + f4i - 8));
                    }
                }
            }
            CP_COMMIT();
        }
        __syncthreads();

        // ---- stage B: GEMM1 (FFMA, K=8) -> packed A fragment unit k=nq ----
        {
            const int nb = nq * 16;
            float acc[2][2][2];
            #pragma unroll
            for (int a = 0; a < 2; a++)
                #pragma unroll
                for (int b = 0; b < 2; b++) { acc[a][b][0] = 0.f; acc[a][b][1] = 0.f; }
            #pragma unroll
            for (int k = 0; k < 8; k++) {
                float e0v = sm[OFF_EMBT + k*TE + mb + g];
                float e1v = sm[OFF_EMBT + k*TE + mb + 8 + g];
                #pragma unroll
                for (int nt = 0; nt < 2; nt++) {
                    float2 wv = *(const float2*)(sm + OFF_W0 + k*64 + nb + nt*8 + 2*tq);
                    acc[0][nt][0] += e0v * wv.x; acc[0][nt][1] += e0v * wv.y;
                    acc[1][nt][0] += e1v * wv.x; acc[1][nt][1] += e1v * wv.y;
                }
            }
            uint32_t h0,l0,h1,l1,h2,l2,h3,l3;
            split2(swishf(acc[0][0][0]), swishf(acc[0][0][1]), h0, l0);
            split2(swishf(acc[1][0][0]), swishf(acc[1][0][1]), h1, l1);
            split2(swishf(acc[0][1][0]), swishf(acc[0][1][1]), h2, l2);
            split2(swishf(acc[1][1][0]), swishf(acc[1][1][1]), h3, l3);
            *(uint4*)(abh + nq * 128) = make_uint4(h0, h1, h2, h3);
            *(uint4*)(abl + nq * 128) = make_uint4(l0, l1, l2, l3);
        }
        CP_WAIT0();
        __syncthreads();   // A-frags + gathered svs all visible

        // ---- dots (2 per thread), overlapped with stage C MMA phase ----
        {
            const float* usf = sm + OFF_US + 4 * ge;
            float ux = usf[0], uy = usf[1], uz = usf[2];
            #pragma unroll
            for (int q = 0; q < 2; q++) {
                int c = 2 * gsub + q;
                const float* vv = gdst + 32 + 3 * c;
                sm[OFF_DOTS + ge * 20 + c] = ux*vv[0] + uy*vv[1] + uz*vv[2];
            }
        }

        // ---- stage C: GEMM2 via bf16 mma (3-pass split) ----
        float acc2[2][4];
        {
            #pragma unroll
            for (int n = 0; n < 2; n++)
                #pragma unroll
                for (int j = 0; j < 4; j++) acc2[n][j] = 0.f;
            #pragma unroll
            for (int k = 0; k < 4; k++) {
                const int kk = (k + r2) & 3;
                uint4 ah = *(const uint4*)(abh + k * 128);
                uint4 al = *(const uint4*)(abl + k * 128);
                uint4 b0 = *(const uint4*)(bb2 + kk * 16);
                uint4 b1 = *(const uint4*)(bb2 + 512 + kk * 16);
                mma_bf16(acc2[0], ah.x, ah.y, ah.z, ah.w, b0.x, b0.y);
                mma_bf16(acc2[1], ah.x, ah.y, ah.z, ah.w, b1.x, b1.y);
                mma_bf16(acc2[0], ah.x, ah.y, ah.z, ah.w, b0.z, b0.w);
                mma_bf16(acc2[1], ah.x, ah.y, ah.z, ah.w, b1.z, b1.w);
                mma_bf16(acc2[0], al.x, al.y, al.z, al.w, b0.x, b0.y);
                mma_bf16(acc2[1], al.x, al.y, al.z, al.w, b1.x, b1.y);
            }
        }
        __syncthreads();   // all h1 reads done before overwrite

        // ---- stage D: swish(h2), split -> packed A fragment unit k=nq ----
        {
            uint32_t h0,l0,h1,l1,h2,l2,h3,l3;
            split2(swishf(acc2[0][0]), swishf(acc2[0][1]), h0, l0);
            split2(swishf(acc2[0][2]), swishf(acc2[0][3]), h1, l1);
            split2(swishf(acc2[1][0]), swishf(acc2[1][1]), h2, l2);
            split2(swishf(acc2[1][2]), swishf(acc2[1][3]), h3, l3);
            *(uint4*)(abh + nq * 128) = make_uint4(h0, h1, h2, h3);
            *(uint4*)(abl + nq * 128) = make_uint4(l0, l1, l2, l3);
        }
        __syncthreads();

        // ---- stage E: GEMM3 via bf16 mma (3-pass split) -> mixs ----
        {
            float acc3[4][4];
            #pragma unroll
            for (int n = 0; n < 4; n++)
                #pragma unroll
                for (int j = 0; j < 4; j++) acc3[n][j] = 0.f;
            #pragma unroll
            for (int k = 0; k < 4; k++) {
                const int kk = (k + r3) & 3;
                uint4 ah = *(const uint4*)(abh + k * 128);
                uint4 al = *(const uint4*)(abl + k * 128);
                uint4 b[4];
                #pragma unroll
                for (int n = 0; n < 4; n++)
                    if (n < nt3) b[n] = *(const uint4*)(bb3 + n * 512 + kk * 16);
                #pragma unroll
                for (int n = 0; n < 4; n++)
                    if (n < nt3) mma_bf16(acc3[n], ah.x, ah.y, ah.z, ah.w, b[n].x, b[n].y);
                #pragma unroll
                for (int n = 0; n < 4; n++)
                    if (n < nt3) mma_bf16(acc3[n], ah.x, ah.y, ah.z, ah.w, b[n].z, b[n].w);
                #pragma unroll
                for (int n = 0; n < 4; n++)
                    if (n < nt3) mma_bf16(acc3[n], al.x, al.y, al.z, al.w, b[n].x, b[n].y);
            }
            __syncthreads();   // A/EMBT fully read before gate store aliases them
            #pragma unroll
            for (int n = 0; n < 4; n++) {
                if (n < nt3) {
                    int col = nb3 + n*8 + 2*tq;
                    *(float2*)(sm + OFF_MIXS + (mb + g) * MIX_STRIDE + col) =
                        make_float2(acc3[n][0], acc3[n][1]);
                    *(float2*)(sm + OFF_MIXS + (mb + g + 8) * MIX_STRIDE + col) =
                        make_float2(acc3[n][2], acc3[n][3]);
                }
            }
        }
        __syncthreads();

        // ---- stage G: message formation + atomic scatter, 8 threads/edge ----
        {
            const int e = ge, sub = gsub;
            const int eg2 = e0 + e;
            const bool ok = (eg2 < E);
            int rec = ok ? receivers[eg2] : 0;
            const float* dst = gdst;
            const float* usf = sm + OFF_US + 4 * e;
            const float* dts = sm + OFF_DOTS + e * 20;
            const float* mx  = sm + OFF_MIXS + e * MIX_STRIDE;
            float* obase = out + (size_t)rec * 240;
            const float ux = usf[0], uy = usf[1], uz = usf[2];

            #pragma unroll
            for (int it = 0; it < 8; it++) {
                const int gg = 8 * it + sub;              // 0..63, valid < 60
                if (it == 7 && sub >= 4) break;
                float4 val;
                if (gg < 8) {                 // msg_s: s * gate
                    float4 s4 = *(const float4*)(dst + 4 * gg);
                    float4 m4 = *(const float4*)(mx + 4 * gg);
                    val.x = s4.x*m4.x; val.y = s4.y*m4.y; val.z = s4.z*m4.z; val.w = s4.w*m4.w;
                } else if (gg < 12) {         // msg_s: (v.u) * gate
                    float4 d4 = *(const float4*)(dts + 4 * (gg - 8));
                    float4 m4 = *(const float4*)(mx + 4 * gg);
                    val.x = d4.x*m4.x; val.y = d4.y*m4.y; val.z = d4.z*m4.z; val.w = d4.w*m4.w;
                } else {                      // msg_v flat regions
                    const int j0 = 4 * gg - 48;
                    const int ch0 = j0 / 3;
                    const int i0 = j0 - 3 * ch0;
                    const float m0 = mx[48 + ch0];
                    const float m1 = mx[48 + ch0 + 1];
                    float tmp[4];
                    if (gg < 24) {            // filtered v (ch 0..15)
                        float4 vv = *(const float4*)(dst + 32 + j0);
                        float vvq[4] = {vv.x, vv.y, vv.z, vv.w};
                        #pragma unroll
                        for (int q = 0; q < 4; q++) {
                            bool cross = (i0 + q) >= 3;
                            tmp[q] = vvq[q] * (cross ? m1 : m0);
                        }
                    } else if (gg < 48) {     // s x Y1 (ch 16..47)
                        float s0 = dst[ch0 - 16];
                        float s1 = dst[ch0 - 15];
                        #pragma unroll
                        for (int q = 0; q < 4; q++) {
                            bool cross = (i0 + q) >= 3;
                            int i = i0 + q - (cross ? 3 : 0);
                            float u = (i == 0) ? ux : ((i == 1) ? uy : uz);
                            tmp[q] = (cross ? s1 : s0) * u * (cross ? m1 : m0);
                        }
                    } else {                  // v x Y2 (ch 48..63), sqrt1.5 folded in gate
                        int jj = j0 - 144;
                        float4 vv = *(const float4*)(dst + 32 + jj);
                        float vvq[4] = {vv.x, vv.y, vv.z, vv.w};
                        float d0 = dts[ch0 - 48];
                        float d1 = dts[ch0 - 47];
                        #pragma unroll
                        for (int q = 0; q < 4; q++) {
                            bool cross = (i0 + q) >= 3;
                            int i = i0 + q - (cross ? 3 : 0);
                            float u = (i == 0) ? ux : ((i == 1) ? uy : uz);
                            float dd = cross ? d1 : d0;
                            tmp[q] = (u * dd - vvq[q] * 0.3333333333333333f) * (cross ? m1 : m0);
                        }
                    }
                    val.x = tmp[0]; val.y = tmp[1]; val.z = tmp[2]; val.w = tmp[3];
                }
                if (ok) {
                    float* addr = obase + 4 * gg;
                    asm volatile("red.global.add.v4.f32 [%0], {%1,%2,%3,%4};"
                                 :: "l"(addr), "f"(val.x), "f"(val.y), "f"(val.z), "f"(val.w)
                                 : "memory");
                }
            }
        }
        __syncthreads();   // smem reused next tile
    }
}

extern "C" void kernel_launch(void* const* d_in, const int* in_sizes, int n_in,
                              void* d_out, int out_size) {
    const float* vectors   = (const float*)d_in[0];
    const float* node_s    = (const float*)d_in[1];
    const float* node_v    = (const float*)d_in[2];
    const float* W0        = (const float*)d_in[3];
    const float* W1        = (const float*)d_in[4];
    const float* W2        = (const float*)d_in[5];
    const int*   senders   = (const int*)d_in[6];
    const int*   receivers = (const int*)d_in[7];
    float*       out       = (float*)d_out;

    int E = in_sizes[6];
    int numTiles = (E + TE - 1) / TE;

    cudaFuncSetAttribute(mp_kernel, cudaFuncAttributeMaxDynamicSharedMemorySize, SMEM_BYTES);

    cudaMemsetAsync(d_out, 0, (size_t)out_size * sizeof(float), 0);

    int grid = 296;                      // persistent: 2 CTAs/SM, 32 warps/SM
    if (grid > numTiles) grid = numTiles;
    mp_kernel<<<grid, THREADS, SMEM_BYTES>>>(vectors, node_s, node_v, W0, W1, W2,
                                             senders, receivers, out, E, numTiles);
}

// round 14
// speedup vs baseline: 1.1366x; 1.0086x over previous
#include <cuda_runtime.h>
#include <cuda_bf16.h>
#include <math.h>
#include <stdint.h>

#define TE 64
#define THREADS 512
#define ESTR 72   // EMBT row stride (conflict-free for distributed stage A)

// ---- smem layout (32-bit word offsets) ----
#define OFF_W0    0        // fp32 [8][64] folded 1/sqrt(8)               512
#define OFF_B2    512      // packed units [64 n][4 k][4 tq][16B]         4096
#define OFF_B3    4608     // packed units [112 n][4 k][4 tq][16B]        7168
// union region: A-frags + EMBT alias MIXS
#define OFF_AHI   11776    // A hi frag units [4 ms][4 k][8 g][4 tq]      2048
#define OFF_ALO   13824    // A lo                                        2048
#define OFF_EMBT  15872    // fp32 [8][72]                                576
#define OFF_MIXS  11776    // fp32 [64][116] gates (aliases above)        7424
#define OFF_US    19200    // [64][4]                                     256
#define OFF_SVS   19456    // [64][84]                                    5376
#define OFF_DOTS  24832    // [64][20] (stride 20: conflict-free)         1280
#define MIX_STRIDE 116
#define SMEM_FLOATS 26112
#define SMEM_BYTES (SMEM_FLOATS * 4)   // 104448 B -> 2 CTAs/SM

__device__ __forceinline__ float swishf(float x) {
    return x * (1.0f / (1.0f + __expf(-x)));
}

__device__ __forceinline__ void split2(float x0, float x1, uint32_t& h, uint32_t& l) {
    __nv_bfloat162 hb = __floats2bfloat162_rn(x0, x1);
    float r0 = x0 - __bfloat162float(hb.x);
    float r1 = x1 - __bfloat162float(hb.y);
    __nv_bfloat162 lb = __floats2bfloat162_rn(r0, r1);
    h = *(uint32_t*)&hb;
    l = *(uint32_t*)&lb;
}

__device__ __forceinline__ void mma_bf16(float* d, uint32_t a0, uint32_t a1,
                                         uint32_t a2, uint32_t a3,
                                         uint32_t b0, uint32_t b1) {
    asm volatile(
        "mma.sync.aligned.m16n8k16.row.col.f32.bf16.bf16.f32 "
        "{%0,%1,%2,%3}, {%4,%5,%6,%7}, {%8,%9}, {%0,%1,%2,%3};"
        : "+f"(d[0]), "+f"(d[1]), "+f"(d[2]), "+f"(d[3])
        : "r"(a0), "r"(a1), "r"(a2), "r"(a3), "r"(b0), "r"(b1));
}

extern "C" __global__ void __launch_bounds__(THREADS, 2)
mp_kernel(const float* __restrict__ vectors,
          const float* __restrict__ node_s,
          const float* __restrict__ node_v,
          const float* __restrict__ W0,
          const float* __restrict__ W1,
          const float* __restrict__ W2,
          const int* __restrict__ senders,
          const int* __restrict__ receivers,
          float* __restrict__ out,
          int E, int numTiles)
{
    extern __shared__ float sm[];
    uint32_t* smw = (uint32_t*)sm;
    const int t = threadIdx.x;

    // ---- one-time weight staging (packed 16B units, swizzled) ----
    for (int i = t; i < 512; i += THREADS) sm[OFF_W0 + i] = W0[i] * 0.35355339059327373f;
    for (int i = t; i < 64 * 32; i += THREADS) {      // B2[n][k] = W1[k][n]/8
        int n = i >> 5, wd = i & 31;
        int k = wd >> 3, r = wd & 7, tq = r & 3, half = r >> 2;
        float x0 = W1[(2*wd)   * 64 + n] * 0.125f;
        float x1 = W1[(2*wd+1) * 64 + n] * 0.125f;
        uint32_t hw, lw;
        split2(x0, x1, hw, lw);
        int kk = (k + n) & 3;
        int base = OFF_B2 + (n * 16 + kk * 4 + tq) * 4;
        smw[base + half] = hw;
        smw[base + 2 + half] = lw;
    }
    for (int i = t; i < 112 * 32; i += THREADS) {     // B3[n][k] = W2[k][n]*scl(n)
        int n = i >> 5, wd = i & 31;
        int k = wd >> 3, r = wd & 7, tq = r & 3, half = r >> 2;
        float scl = (n >= 96) ? 0.03125f * 1.224744871391589f : 0.03125f;
        float x0 = W2[(2*wd)   * 112 + n] * scl;
        float x1 = W2[(2*wd+1) * 112 + n] * scl;
        uint32_t hw, lw;
        split2(x0, x1, hw, lw);
        int kk = (k + n) & 3;
        int base = OFF_B3 + (n * 16 + kk * 4 + tq) * 4;
        smw[base + half] = hw;
        smw[base + 2 + half] = lw;
    }
    __syncthreads();

    const int w = t >> 5, lane = t & 31;
    const int g = lane >> 2, tq = lane & 3;
    const int ms = w >> 2, nq = w & 3;           // 4 M-strips x 4 N-quarters
    const int mb = ms * 16;
    const int aunit0 = (ms * 128 + g * 4 + tq) * 4;   // + k*128 words

    // thread-constant base pointers
    const uint32_t* abh = smw + OFF_AHI + aunit0;
    const uint32_t* abl = smw + OFF_ALO + aunit0;
    const int nb2 = nq * 16;
    const int r2 = (nb2 + g) & 3;
    const uint32_t* bb2 = smw + OFF_B2 + (nb2 + g) * 64 + tq * 4;   // + n*512 + kk*16
    const int nb3 = (nq < 2) ? 32 * nq : 64 + 24 * (nq - 2);
    const int nt3 = (nq < 2) ? 4 : 3;
    const int r3 = (nb3 + g) & 3;
    const uint32_t* bb3 = smw + OFF_B3 + (nb3 + g) * 64 + tq * 4;   // + n*512 + kk*16

    // per-edge identity (8 threads/edge)
    const int ge = t >> 3, gsub = t & 7;
    float* gdst = sm + OFF_SVS + ge * 84;

    for (int tile = blockIdx.x; tile < numTiles; tile += gridDim.x) {
        const int e0 = tile * TE;
        const int geg = e0 + ge;
        const bool gok = (geg < E);

        // prefetch receiver index for stage G (hide L2 latency)
        int rec = gok ? receivers[geg] : 0;

        // ---- stage A (distributed, 8 threads/edge): geometry + radial basis ----
        {
            float vx = 0.f, vy = 0.f, vz = 0.f;
            if (gok) { vx = vectors[3*geg+0]; vy = vectors[3*geg+1]; vz = vectors[3*geg+2]; }
            float r = sqrtf(vx*vx + vy*vy + vz*vz);
            float rinv = (r > 1e-12f) ? 1.0f / r : 0.0f;
            if (gsub == 0) {
                *(float4*)(sm + OFF_US + 4*ge) = make_float4(vx*rinv, vy*rinv, vz*rinv, 0.f);
            }
            float env = 0.0f;
            if (r < 1.0f) {
                float x2 = r*r, x4 = x2*x2, x6 = x4*x2, x7 = x6*r, x8 = x4*x4;
                env = 1.0f - 28.0f*x6 + 48.0f*x7 - 21.0f*x8;
            }
            float pref = (r > 0.0f) ? 1.4142135623730951f * rinv * env : 0.0f;
            float sn = sinf((float)(gsub + 1) * 3.14159265358979323846f * r);
            sm[OFF_EMBT + gsub * ESTR + ge] = pref * sn;
        }
        // gather issue (latency hidden behind stage B), 8 threads/edge
        int snd = gok ? senders[geg] : 0;
        const float4* sp4 = (const float4*)(node_s + (size_t)snd * 32);
        const float4* vp4 = (const float4*)(node_v + (size_t)snd * 48);
        float4 gr[3];
        #pragma unroll
        for (int q = 0; q < 3; q++) {
            int f4i = gsub + 8*q;                 // 0..23, valid < 20
            float4 val = {0.f, 0.f, 0.f, 0.f};
            if (gok && f4i < 20) val = (f4i < 8) ? sp4[f4i] : vp4[f4i - 8];
            gr[q] = val;
        }
        __syncthreads();

        // ---- stage B: GEMM1 (FFMA, K=8) -> packed A fragment unit k=nq ----
        {
            const int nb = nq * 16;
            float acc[2][2][2];
            #pragma unroll
            for (int a = 0; a < 2; a++)
                #pragma unroll
                for (int b = 0; b < 2; b++) { acc[a][b][0] = 0.f; acc[a][b][1] = 0.f; }
            #pragma unroll
            for (int k = 0; k < 8; k++) {
                float e0v = sm[OFF_EMBT + k*ESTR + mb + g];
                float e1v = sm[OFF_EMBT + k*ESTR + mb + 8 + g];
                #pragma unroll
                for (int nt = 0; nt < 2; nt++) {
                    float2 wv = *(const float2*)(sm + OFF_W0 + k*64 + nb + nt*8 + 2*tq);
                    acc[0][nt][0] += e0v * wv.x; acc[0][nt][1] += e0v * wv.y;
                    acc[1][nt][0] += e1v * wv.x; acc[1][nt][1] += e1v * wv.y;
                }
            }
            uint32_t h0,l0,h1,l1,h2,l2,h3,l3;
            split2(swishf(acc[0][0][0]), swishf(acc[0][0][1]), h0, l0);
            split2(swishf(acc[1][0][0]), swishf(acc[1][0][1]), h1, l1);
            split2(swishf(acc[0][1][0]), swishf(acc[0][1][1]), h2, l2);
            split2(swishf(acc[1][1][0]), swishf(acc[1][1][1]), h3, l3);
            *(uint4*)(abh + nq * 128) = make_uint4(h0, h1, h2, h3);
            *(uint4*)(abl + nq * 128) = make_uint4(l0, l1, l2, l3);
        }
        // land gather into smem; compute dots (2 per thread)
        {
            #pragma unroll
            for (int q = 0; q < 3; q++) {
                int f4i = gsub + 8*q;
                if (f4i < 20) *(float4*)(gdst + 4 * f4i) = gr[q];
            }
            __syncwarp();
            const float* usf = sm + OFF_US + 4 * ge;
            float ux = usf[0], uy = usf[1], uz = usf[2];
            #pragma unroll
            for (int q = 0; q < 2; q++) {
                int c = 2 * gsub + q;
                const float* vv = gdst + 32 + 3 * c;
                sm[OFF_DOTS + ge * 20 + c] = ux*vv[0] + uy*vv[1] + uz*vv[2];
            }
        }
        __syncthreads();

        // ---- stage C: GEMM2 via bf16 mma (3-pass split, pass-interleaved) ----
        float acc2[2][4];
        {
            #pragma unroll
            for (int n = 0; n < 2; n++)
                #pragma unroll
                for (int j = 0; j < 4; j++) acc2[n][j] = 0.f;
            #pragma unroll
            for (int k = 0; k < 4; k++) {
                const int kk = (k + r2) & 3;
                uint4 ah = *(const uint4*)(abh + k * 128);
                uint4 al = *(const uint4*)(abl + k * 128);
                uint4 b0 = *(const uint4*)(bb2 + kk * 16);
                uint4 b1 = *(const uint4*)(bb2 + 512 + kk * 16);
                mma_bf16(acc2[0], ah.x, ah.y, ah.z, ah.w, b0.x, b0.y);
                mma_bf16(acc2[1], ah.x, ah.y, ah.z, ah.w, b1.x, b1.y);
                mma_bf16(acc2[0], ah.x, ah.y, ah.z, ah.w, b0.z, b0.w);
                mma_bf16(acc2[1], ah.x, ah.y, ah.z, ah.w, b1.z, b1.w);
                mma_bf16(acc2[0], al.x, al.y, al.z, al.w, b0.x, b0.y);
                mma_bf16(acc2[1], al.x, al.y, al.z, al.w, b1.x, b1.y);
            }
        }
        __syncthreads();   // all h1 reads done before overwrite

        // ---- stage D: swish(h2), split -> packed A fragment unit k=nq ----
        {
            uint32_t h0,l0,h1,l1,h2,l2,h3,l3;
            split2(swishf(acc2[0][0]), swishf(acc2[0][1]), h0, l0);
            split2(swishf(acc2[0][2]), swishf(acc2[0][3]), h1, l1);
            split2(swishf(acc2[1][0]), swishf(acc2[1][1]), h2, l2);
            split2(swishf(acc2[1][2]), swishf(acc2[1][3]), h3, l3);
            *(uint4*)(abh + nq * 128) = make_uint4(h0, h1, h2, h3);
            *(uint4*)(abl + nq * 128) = make_uint4(l0, l1, l2, l3);
        }
        __syncthreads();

        // ---- stage E: GEMM3 via bf16 mma (3-pass split, pass-interleaved) ----
        {
            float acc3[4][4];
            #pragma unroll
            for (int n = 0; n < 4; n++)
                #pragma unroll
                for (int j = 0; j < 4; j++) acc3[n][j] = 0.f;
            #pragma unroll
            for (int k = 0; k < 4; k++) {
                const int kk = (k + r3) & 3;
                uint4 ah = *(const uint4*)(abh + k * 128);
                uint4 al = *(const uint4*)(abl + k * 128);
                uint4 b[4];
                #pragma unroll
                for (int n = 0; n < 4; n++)
                    if (n < nt3) b[n] = *(const uint4*)(bb3 + n * 512 + kk * 16);
                #pragma unroll
                for (int n = 0; n < 4; n++)
                    if (n < nt3) mma_bf16(acc3[n], ah.x, ah.y, ah.z, ah.w, b[n].x, b[n].y);
                #pragma unroll
                for (int n = 0; n < 4; n++)
                    if (n < nt3) mma_bf16(acc3[n], ah.x, ah.y, ah.z, ah.w, b[n].z, b[n].w);
                #pragma unroll
                for (int n = 0; n < 4; n++)
                    if (n < nt3) mma_bf16(acc3[n], al.x, al.y, al.z, al.w, b[n].x, b[n].y);
            }
            __syncthreads();   // A/EMBT fully read before gate store aliases them
            #pragma unroll
            for (int n = 0; n < 4; n++) {
                if (n < nt3) {
                    int col = nb3 + n*8 + 2*tq;
                    *(float2*)(sm + OFF_MIXS + (mb + g) * MIX_STRIDE + col) =
                        make_float2(acc3[n][0], acc3[n][1]);
                    *(float2*)(sm + OFF_MIXS + (mb + g + 8) * MIX_STRIDE + col) =
                        make_float2(acc3[n][2], acc3[n][3]);
                }
            }
        }
        __syncthreads();

        // ---- stage G: message formation + atomic scatter, 8 threads/edge ----
        {
            const int sub = gsub;
            const bool ok = gok;
            const float* dst = gdst;
            const float* usf = sm + OFF_US + 4 * ge;
            const float* dts = sm + OFF_DOTS + ge * 20;
            const float* mx  = sm + OFF_MIXS + ge * MIX_STRIDE;
            float* obase = out + (size_t)rec * 240;
            const float ux = usf[0], uy = usf[1], uz = usf[2];

            #pragma unroll
            for (int it = 0; it < 8; it++) {
                const int gg = 8 * it + sub;              // 0..63, valid < 60
                if (it == 7 && sub >= 4) break;
                float4 val;
                if (gg < 8) {                 // msg_s: s * gate
                    float4 s4 = *(const float4*)(dst + 4 * gg);
                    float4 m4 = *(const float4*)(mx + 4 * gg);
                    val.x = s4.x*m4.x; val.y = s4.y*m4.y; val.z = s4.z*m4.z; val.w = s4.w*m4.w;
                } else if (gg < 12) {         // msg_s: (v.u) * gate
                    float4 d4 = *(const float4*)(dts + 4 * (gg - 8));
                    float4 m4 = *(const float4*)(mx + 4 * gg);
                    val.x = d4.x*m4.x; val.y = d4.y*m4.y; val.z = d4.z*m4.z; val.w = d4.w*m4.w;
                } else {                      // msg_v flat regions
                    const int j0 = 4 * gg - 48;
                    const int ch0 = j0 / 3;
                    const int i0 = j0 - 3 * ch0;
                    const float m0 = mx[48 + ch0];
                    const float m1 = mx[48 + ch0 + 1];
                    float tmp[4];
                    if (gg < 24) {            // filtered v (ch 0..15)
                        float4 vv = *(const float4*)(dst + 32 + j0);
                        float vvq[4] = {vv.x, vv.y, vv.z, vv.w};
                        #pragma unroll
                        for (int q = 0; q < 4; q++) {
                            bool cross = (i0 + q) >= 3;
                            tmp[q] = vvq[q] * (cross ? m1 : m0);
                        }
                    } else if (gg < 48) {     // s x Y1 (ch 16..47)
                        float s0 = dst[ch0 - 16];
                        float s1 = dst[ch0 - 15];
                        #pragma unroll
                        for (int q = 0; q < 4; q++) {
                            bool cross = (i0 + q) >= 3;
                            int i = i0 + q - (cross ? 3 : 0);
                            float u = (i == 0) ? ux : ((i == 1) ? uy : uz);
                            tmp[q] = (cross ? s1 : s0) * u * (cross ? m1 : m0);
                        }
                    } else {                  // v x Y2 (ch 48..63), sqrt1.5 folded in gate
                        int jj = j0 - 144;
                        float4 vv = *(const float4*)(dst + 32 + jj);
                        float vvq[4] = {vv.x, vv.y, vv.z, vv.w};
                        float d0 = dts[ch0 - 48];
                        float d1 = dts[ch0 - 47];
                        #pragma unroll
                        for (int q = 0; q < 4; q++) {
                            bool cross = (i0 + q) >= 3;
                            int i = i0 + q - (cross ? 3 : 0);
                            float u = (i == 0) ? ux : ((i == 1) ? uy : uz);
                            float dd = cross ? d1 : d0;
                            tmp[q] = (u * dd - vvq[q] * 0.3333333333333333f) * (cross ? m1 : m0);
                        }
                    }
                    val.x = tmp[0]; val.y = tmp[1]; val.z = tmp[2]; val.w = tmp[3];
                }
                if (ok) {
                    float* addr = obase + 4 * gg;
                    asm volatile("red.global.add.v4.f32 [%0], {%1,%2,%3,%4};"
                                 :: "l"(addr), "f"(val.x), "f"(val.y), "f"(val.z), "f"(val.w)
                                 : "memory");
                }
            }
        }
        __syncthreads();   // smem reused next tile
    }
}

extern "C" void kernel_launch(void* const* d_in, const int* in_sizes, int n_in,
                              void* d_out, int out_size) {
    const float* vectors   = (const float*)d_in[0];
    const float* node_s    = (const float*)d_in[1];
    const float* node_v    = (const float*)d_in[2];
    const float* W0        = (const float*)d_in[3];
    const float* W1        = (const float*)d_in[4];
    const float* W2        = (const float*)d_in[5];
    const int*   senders   = (const int*)d_in[6];
    const int*   receivers = (const int*)d_in[7];
    float*       out       = (float*)d_out;

    int E = in_sizes[6];
    int numTiles = (E + TE - 1) / TE;

    cudaFuncSetAttribute(mp_kernel, cudaFuncAttributeMaxDynamicSharedMemorySize, SMEM_BYTES);

    cudaMemsetAsync(d_out, 0, (size_t)out_size * sizeof(float), 0);

    int grid = 296;                      // persistent: 2 CTAs/SM, 32 warps/SM
    if (grid > numTiles) grid = numTiles;
    mp_kernel<<<grid, THREADS, SMEM_BYTES>>>(vectors, node_s, node_v, W0, W1, W2,
                                             senders, receivers, out, E, numTiles);
}

// round 15
// speedup vs baseline: 1.1625x; 1.0228x over previous
#include <cuda_runtime.h>
#include <cuda_bf16.h>
#include <math.h>
#include <stdint.h>

#define TE 64
#define THREADS 512
#define ESTR 68   // EMBT row stride: (136*tq+g) mod 32 distinct -> conflict-free

// ---- smem layout (32-bit word offsets) ----
#define OFF_W0    0        // packed W0 units [64 n][4 tq-swz][16B]       1024
#define OFF_B2    1024     // packed units [64 n][4 k][4 tq][16B]         4096
#define OFF_B3    5120     // packed units [112 n][4 k][4 tq][16B]        7168
// union region: A-frags + EMBT alias MIXS
#define OFF_AHI   12288    // A hi frag units [4 ms][4 k][8 g][4 tq]      2048
#define OFF_ALO   14336    // A lo                                        2048
#define OFF_EMBT  16384    // fp32 [8][68]                                544
#define OFF_MIXS  12288    // fp32 [64][116] gates (aliases above)        7424
#define OFF_US    19712    // [64][4]                                     256
#define OFF_SVS   19968    // [64][84]                                    5376
#define OFF_DOTS  25344    // [64][20] (stride 20: conflict-free)         1280
#define MIX_STRIDE 116
#define SMEM_FLOATS 26624
#define SMEM_BYTES (SMEM_FLOATS * 4)   // 106496 B -> 2 CTAs/SM

__device__ __forceinline__ float swishf(float x) {
    return x * (1.0f / (1.0f + __expf(-x)));
}

__device__ __forceinline__ void split2(float x0, float x1, uint32_t& h, uint32_t& l) {
    __nv_bfloat162 hb = __floats2bfloat162_rn(x0, x1);
    float r0 = x0 - __bfloat162float(hb.x);
    float r1 = x1 - __bfloat162float(hb.y);
    __nv_bfloat162 lb = __floats2bfloat162_rn(r0, r1);
    h = *(uint32_t*)&hb;
    l = *(uint32_t*)&lb;
}

__device__ __forceinline__ void mma_bf16(float* d, uint32_t a0, uint32_t a1,
                                         uint32_t a2, uint32_t a3,
                                         uint32_t b0, uint32_t b1) {
    asm volatile(
        "mma.sync.aligned.m16n8k16.row.col.f32.bf16.bf16.f32 "
        "{%0,%1,%2,%3}, {%4,%5,%6,%7}, {%8,%9}, {%0,%1,%2,%3};"
        : "+f"(d[0]), "+f"(d[1]), "+f"(d[2]), "+f"(d[3])
        : "r"(a0), "r"(a1), "r"(a2), "r"(a3), "r"(b0), "r"(b1));
}

extern "C" __global__ void __launch_bounds__(THREADS, 2)
mp_kernel(const float* __restrict__ vectors,
          const float* __restrict__ node_s,
          const float* __restrict__ node_v,
          const float* __restrict__ W0,
          const float* __restrict__ W1,
          const float* __restrict__ W2,
          const int* __restrict__ senders,
          const int* __restrict__ receivers,
          float* __restrict__ out,
          int E, int numTiles)
{
    extern __shared__ float sm[];
    uint32_t* smw = (uint32_t*)sm;
    const int t = threadIdx.x;

    // ---- one-time weight staging (packed 16B units, swizzled) ----
    for (int i = t; i < 256; i += THREADS) {          // W0 units: k16-padded (half zero)
        int n = i >> 2, q = i & 3;
        float x0 = W0[(2*q)   * 64 + n] * 0.35355339059327373f;
        float x1 = W0[(2*q+1) * 64 + n] * 0.35355339059327373f;
        uint32_t hw, lw;
        split2(x0, x1, hw, lw);
        int base = OFF_W0 + (n * 4 + ((q + n) & 3)) * 4;
        smw[base + 0] = hw; smw[base + 1] = 0u;
        smw[base + 2] = lw; smw[base + 3] = 0u;
    }
    for (int i = t; i < 64 * 32; i += THREADS) {      // B2[n][k] = W1[k][n]/8
        int n = i >> 5, wd = i & 31;
        int k = wd >> 3, r = wd & 7, tq = r & 3, half = r >> 2;
        float x0 = W1[(2*wd)   * 64 + n] * 0.125f;
        float x1 = W1[(2*wd+1) * 64 + n] * 0.125f;
        uint32_t hw, lw;
        split2(x0, x1, hw, lw);
        int kk = (k + n) & 3;
        int base = OFF_B2 + (n * 16 + kk * 4 + tq) * 4;
        smw[base + half] = hw;
        smw[base + 2 + half] = lw;
    }
    for (int i = t; i < 112 * 32; i += THREADS) {     // B3[n][k] = W2[k][n]*scl(n)
        int n = i >> 5, wd = i & 31;
        int k = wd >> 3, r = wd & 7, tq = r & 3, half = r >> 2;
        float scl = (n >= 96) ? 0.03125f * 1.224744871391589f : 0.03125f;
        float x0 = W2[(2*wd)   * 112 + n] * scl;
        float x1 = W2[(2*wd+1) * 112 + n] * scl;
        uint32_t hw, lw;
        split2(x0, x1, hw, lw);
        int kk = (k + n) & 3;
        int base = OFF_B3 + (n * 16 + kk * 4 + tq) * 4;
        smw[base + half] = hw;
        smw[base + 2 + half] = lw;
    }
    __syncthreads();

    const int w = t >> 5, lane = t & 31;
    const int g = lane >> 2, tq = lane & 3;
    const int ms = w >> 2, nq = w & 3;           // 4 M-strips x 4 N-quarters
    const int mb = ms * 16;
    const int aunit0 = (ms * 128 + g * 4 + tq) * 4;   // + k*128 words

    // thread-constant base pointers
    const uint32_t* abh = smw + OFF_AHI + aunit0;
    const uint32_t* abl = smw + OFF_ALO + aunit0;
    const int nb2 = nq * 16;
    const int r2 = (nb2 + g) & 3;
    const uint32_t* bb2 = smw + OFF_B2 + (nb2 + g) * 64 + tq * 4;   // + n*512 + kk*16
    const int nb3 = (nq < 2) ? 32 * nq : 64 + 24 * (nq - 2);
    const int nt3 = (nq < 2) ? 4 : 3;
    const int r3 = (nb3 + g) & 3;
    const uint32_t* bb3 = smw + OFF_B3 + (nb3 + g) * 64 + tq * 4;   // + n*512 + kk*16
    // GEMM1: emb reads (rows mb+g, mb+g+8; k = 2tq, 2tq+1) and W0 units
    const float* embp = sm + OFF_EMBT + 136 * tq + mb + g;
    const uint32_t* w0u0;
    const uint32_t* w0u1;
    {
        int row0 = nb2 + g;         // h1 col for nt=0
        int row1 = nb2 + 8 + g;     // nt=1
        w0u0 = smw + OFF_W0 + (row0 * 4 + ((tq + row0) & 3)) * 4;
        w0u1 = smw + OFF_W0 + (row1 * 4 + ((tq + row1) & 3)) * 4;
    }

    // per-edge identity (8 threads/edge)
    const int ge = t >> 3, gsub = t & 7;
    float* gdst = sm + OFF_SVS + ge * 84;

    for (int tile = blockIdx.x; tile < numTiles; tile += gridDim.x) {
        const int e0 = tile * TE;
        const int geg = e0 + ge;
        const bool gok = (geg < E);

        // prefetch receiver index for stage G
        int rec = gok ? receivers[geg] : 0;

        // ---- stage A: geometry + radial embedding (warps 0-1) ----
        if (t < TE) {
            int e = e0 + t;
            float vx = 0.f, vy = 0.f, vz = 0.f;
            if (e < E) { vx = vectors[3*e+0]; vy = vectors[3*e+1]; vz = vectors[3*e+2]; }
            float r = sqrtf(vx*vx + vy*vy + vz*vz);
            float rinv = (r > 1e-12f) ? 1.0f / r : 0.0f;
            sm[OFF_US + 4*t+0] = vx*rinv; sm[OFF_US + 4*t+1] = vy*rinv;
            sm[OFF_US + 4*t+2] = vz*rinv; sm[OFF_US + 4*t+3] = 0.f;
            float env = 0.0f;
            if (r < 1.0f) {
                float x2 = r*r, x4 = x2*x2, x6 = x4*x2, x7 = x6*r, x8 = x4*x4;
                env = 1.0f - 28.0f*x6 + 48.0f*x7 - 21.0f*x8;
            }
            float pref = (r > 0.0f) ? 1.4142135623730951f * rinv * env : 0.0f;
            float s1, c1;
            sincosf(3.14159265358979323846f * r, &s1, &c1);
            float sn = s1, sp = 0.0f, c2 = 2.0f * c1;
            #pragma unroll
            for (int n = 0; n < 8; n++) {
                sm[OFF_EMBT + n*ESTR + t] = pref * sn;
                float nx = c2 * sn - sp; sp = sn; sn = nx;
            }
        }
        // gather issue (latency hidden behind stage B), 8 threads/edge
        int snd = gok ? senders[geg] : 0;
        const float4* sp4 = (const float4*)(node_s + (size_t)snd * 32);
        const float4* vp4 = (const float4*)(node_v + (size_t)snd * 48);
        float4 gr[3];
        #pragma unroll
        for (int q = 0; q < 3; q++) {
            int f4i = gsub + 8*q;                 // 0..23, valid < 20
            float4 val = {0.f, 0.f, 0.f, 0.f};
            if (gok && f4i < 20) val = (f4i < 8) ? sp4[f4i] : vp4[f4i - 8];
            gr[q] = val;
        }
        __syncthreads();

        // ---- stage B: GEMM1 via bf16 mma (K=8 padded to 16), -> A unit k=nq ----
        {
            float e00 = embp[0], e01 = embp[ESTR];          // row mb+g,   k 2tq, 2tq+1
            float e10 = embp[8], e11 = embp[ESTR + 8];      // row mb+g+8
            uint32_t a0h, a0l, a1h, a1l;
            split2(e00, e01, a0h, a0l);
            split2(e10, e11, a1h, a1l);
            float acc1[2][4];
            #pragma unroll
            for (int n = 0; n < 2; n++)
                #pragma unroll
                for (int j = 0; j < 4; j++) acc1[n][j] = 0.f;
            uint4 b0 = *(const uint4*)w0u0;     // [bh0, 0, bl0, 0]
            uint4 b1 = *(const uint4*)w0u1;
            mma_bf16(acc1[0], a0h, a1h, 0u, 0u, b0.x, b0.y);
            mma_bf16(acc1[1], a0h, a1h, 0u, 0u, b1.x, b1.y);
            mma_bf16(acc1[0], a0h, a1h, 0u, 0u, b0.z, b0.w);
            mma_bf16(acc1[1], a0h, a1h, 0u, 0u, b1.z, b1.w);
            mma_bf16(acc1[0], a0l, a1l, 0u, 0u, b0.x, b0.y);
            mma_bf16(acc1[1], a0l, a1l, 0u, 0u, b1.x, b1.y);

            uint32_t h0,l0,h1,l1,h2,l2,h3,l3;
            split2(swishf(acc1[0][0]), swishf(acc1[0][1]), h0, l0);
            split2(swishf(acc1[0][2]), swishf(acc1[0][3]), h1, l1);
            split2(swishf(acc1[1][0]), swishf(acc1[1][1]), h2, l2);
            split2(swishf(acc1[1][2]), swishf(acc1[1][3]), h3, l3);
            *(uint4*)(abh + nq * 128) = make_uint4(h0, h1, h2, h3);
            *(uint4*)(abl + nq * 128) = make_uint4(l0, l1, l2, l3);
        }
        // land gather into smem; compute dots (2 per thread)
        {
            #pragma unroll
            for (int q = 0; q < 3; q++) {
                int f4i = gsub + 8*q;
                if (f4i < 20) *(float4*)(gdst + 4 * f4i) = gr[q];
            }
            __syncwarp();
            const float* usf = sm + OFF_US + 4 * ge;
            float ux = usf[0], uy = usf[1], uz = usf[2];
            #pragma unroll
            for (int q = 0; q < 2; q++) {
                int c = 2 * gsub + q;
                const float* vv = gdst + 32 + 3 * c;
                sm[OFF_DOTS + ge * 20 + c] = ux*vv[0] + uy*vv[1] + uz*vv[2];
            }
        }
        __syncthreads();

        // ---- stage C: GEMM2 via bf16 mma (3-pass split, pass-interleaved) ----
        float acc2[2][4];
        {
            #pragma unroll
            for (int n = 0; n < 2; n++)
                #pragma unroll
                for (int j = 0; j < 4; j++) acc2[n][j] = 0.f;
            #pragma unroll
            for (int k = 0; k < 4; k++) {
                const int kk = (k + r2) & 3;
                uint4 ah = *(const uint4*)(abh + k * 128);
                uint4 al = *(const uint4*)(abl + k * 128);
                uint4 b0 = *(const uint4*)(bb2 + kk * 16);
                uint4 b1 = *(const uint4*)(bb2 + 512 + kk * 16);
                mma_bf16(acc2[0], ah.x, ah.y, ah.z, ah.w, b0.x, b0.y);
                mma_bf16(acc2[1], ah.x, ah.y, ah.z, ah.w, b1.x, b1.y);
                mma_bf16(acc2[0], ah.x, ah.y, ah.z, ah.w, b0.z, b0.w);
                mma_bf16(acc2[1], ah.x, ah.y, ah.z, ah.w, b1.z, b1.w);
                mma_bf16(acc2[0], al.x, al.y, al.z, al.w, b0.x, b0.y);
                mma_bf16(acc2[1], al.x, al.y, al.z, al.w, b1.x, b1.y);
            }
        }
        __syncthreads();   // all h1 reads done before overwrite

        // ---- stage D: swish(h2), split -> packed A fragment unit k=nq ----
        {
            uint32_t h0,l0,h1,l1,h2,l2,h3,l3;
            split2(swishf(acc2[0][0]), swishf(acc2[0][1]), h0, l0);
            split2(swishf(acc2[0][2]), swishf(acc2[0][3]), h1, l1);
            split2(swishf(acc2[1][0]), swishf(acc2[1][1]), h2, l2);
            split2(swishf(acc2[1][2]), swishf(acc2[1][3]), h3, l3);
            *(uint4*)(abh + nq * 128) = make_uint4(h0, h1, h2, h3);
            *(uint4*)(abl + nq * 128) = make_uint4(l0, l1, l2, l3);
        }
        __syncthreads();

        // ---- stage E: GEMM3 via bf16 mma (3-pass split, pass-interleaved) ----
        {
            float acc3[4][4];
            #pragma unroll
            for (int n = 0; n < 4; n++)
                #pragma unroll
                for (int j = 0; j < 4; j++) acc3[n][j] = 0.f;
            #pragma unroll
            for (int k = 0; k < 4; k++) {
                const int kk = (k + r3) & 3;
                uint4 ah = *(const uint4*)(abh + k * 128);
                uint4 al = *(const uint4*)(abl + k * 128);
                uint4 b[4];
                #pragma unroll
                for (int n = 0; n < 4; n++)
                    if (n < nt3) b[n] = *(const uint4*)(bb3 + n * 512 + kk * 16);
                #pragma unroll
                for (int n = 0; n < 4; n++)
                    if (n < nt3) mma_bf16(acc3[n], ah.x, ah.y, ah.z, ah.w, b[n].x, b[n].y);
                #pragma unroll
                for (int n = 0; n < 4; n++)
                    if (n < nt3) mma_bf16(acc3[n], ah.x, ah.y, ah.z, ah.w, b[n].z, b[n].w);
                #pragma unroll
                for (int n = 0; n < 4; n++)
                    if (n < nt3) mma_bf16(acc3[n], al.x, al.y, al.z, al.w, b[n].x, b[n].y);
            }
            __syncthreads();   // A/EMBT fully read before gate store aliases them
            #pragma unroll
            for (int n = 0; n < 4; n++) {
                if (n < nt3) {
                    int col = nb3 + n*8 + 2*tq;
                    *(float2*)(sm + OFF_MIXS + (mb + g) * MIX_STRIDE + col) =
                        make_float2(acc3[n][0], acc3[n][1]);
                    *(float2*)(sm + OFF_MIXS + (mb + g + 8) * MIX_STRIDE + col) =
                        make_float2(acc3[n][2], acc3[n][3]);
                }
            }
        }
        __syncthreads();

        // ---- stage G: message formation + atomic scatter, 8 threads/edge ----
        {
            const int sub = gsub;
            const bool ok = gok;
            const float* dst = gdst;
            const float* usf = sm + OFF_US + 4 * ge;
            const float* dts = sm + OFF_DOTS + ge * 20;
            const float* mx  = sm + OFF_MIXS + ge * MIX_STRIDE;
            float* obase = out + (size_t)rec * 240;
            const float ux = usf[0], uy = usf[1], uz = usf[2];

            #pragma unroll
            for (int it = 0; it < 8; it++) {
                const int gg = 8 * it + sub;              // 0..63, valid < 60
                if (it == 7 && sub >= 4) break;
                float4 val;
                if (gg < 8) {                 // msg_s: s * gate
                    float4 s4 = *(const float4*)(dst + 4 * gg);
                    float4 m4 = *(const float4*)(mx + 4 * gg);
                    val.x = s4.x*m4.x; val.y = s4.y*m4.y; val.z = s4.z*m4.z; val.w = s4.w*m4.w;
                } else if (gg < 12) {         // msg_s: (v.u) * gate
                    float4 d4 = *(const float4*)(dts + 4 * (gg - 8));
                    float4 m4 = *(const float4*)(mx + 4 * gg);
                    val.x = d4.x*m4.x; val.y = d4.y*m4.y; val.z = d4.z*m4.z; val.w = d4.w*m4.w;
                } else {                      // msg_v flat regions
                    const int j0 = 4 * gg - 48;
                    const int ch0 = j0 / 3;
                    const int i0 = j0 - 3 * ch0;
                    const float m0 = mx[48 + ch0];
                    const float m1 = mx[48 + ch0 + 1];
                    float tmp[4];
                    if (gg < 24) {            // filtered v (ch 0..15)
                        float4 vv = *(const float4*)(dst + 32 + j0);
                        float vvq[4] = {vv.x, vv.y, vv.z, vv.w};
                        #pragma unroll
                        for (int q = 0; q < 4; q++) {
                            bool cross = (i0 + q) >= 3;
                            tmp[q] = vvq[q] * (cross ? m1 : m0);
                        }
                    } else if (gg < 48) {     // s x Y1 (ch 16..47)
                        float s0 = dst[ch0 - 16];
                        float s1 = dst[ch0 - 15];
                        #pragma unroll
                        for (int q = 0; q < 4; q++) {
                            bool cross = (i0 + q) >= 3;
                            int i = i0 + q - (cross ? 3 : 0);
                            float u = (i == 0) ? ux : ((i == 1) ? uy : uz);
                            tmp[q] = (cross ? s1 : s0) * u * (cross ? m1 : m0);
                        }
                    } else {                  // v x Y2 (ch 48..63), sqrt1.5 folded in gate
                        int jj = j0 - 144;
                        float4 vv = *(const float4*)(dst + 32 + jj);
                        float vvq[4] = {vv.x, vv.y, vv.z, vv.w};
                        float d0 = dts[ch0 - 48];
                        float d1 = dts[ch0 - 47];
                        #pragma unroll
                        for (int q = 0; q < 4; q++) {
                            bool cross = (i0 + q) >= 3;
                            int i = i0 + q - (cross ? 3 : 0);
                            float u = (i == 0) ? ux : ((i == 1) ? uy : uz);
                            float dd = cross ? d1 : d0;
                            tmp[q] = (u * dd - vvq[q] * 0.3333333333333333f) * (cross ? m1 : m0);
                        }
                    }
                    val.x = tmp[0]; val.y = tmp[1]; val.z = tmp[2]; val.w = tmp[3];
                }
                if (ok) {
                    float* addr = obase + 4 * gg;
                    asm volatile("red.global.add.v4.f32 [%0], {%1,%2,%3,%4};"
                                 :: "l"(addr), "f"(val.x), "f"(val.y), "f"(val.z), "f"(val.w)
                                 : "memory");
                }
            }
        }
        __syncthreads();   // smem reused next tile
    }
}

extern "C" void kernel_launch(void* const* d_in, const int* in_sizes, int n_in,
                              void* d_out, int out_size) {
    const float* vectors   = (const float*)d_in[0];
    const float* node_s    = (const float*)d_in[1];
    const float* node_v    = (const float*)d_in[2];
    const float* W0        = (const float*)d_in[3];
    const float* W1        = (const float*)d_in[4];
    const float* W2        = (const float*)d_in[5];
    const int*   senders   = (const int*)d_in[6];
    const int*   receivers = (const int*)d_in[7];
    float*       out       = (float*)d_out;

    int E = in_sizes[6];
    int numTiles = (E + TE - 1) / TE;

    cudaFuncSetAttribute(mp_kernel, cudaFuncAttributeMaxDynamicSharedMemorySize, SMEM_BYTES);

    cudaMemsetAsync(d_out, 0, (size_t)out_size * sizeof(float), 0);

    int grid = 296;                      // persistent: 2 CTAs/SM, 32 warps/SM
    if (grid > numTiles) grid = numTiles;
    mp_kernel<<<grid, THREADS, SMEM_BYTES>>>(vectors, node_s, node_v, W0, W1, W2,
                                             senders, receivers, out, E, numTiles);
}